// round 1
// baseline (speedup 1.0000x reference)
#include <cuda_runtime.h>

#define THREADS 256
#define OPT 4
#define TILE (THREADS * OPT)      // 1024 outputs per block
#define KMAX 64                   // kernel padded to 64 taps (zeros)
#define SMEM_U (TILE + KMAX)      // 1088 floats; covers tid*4+66 max = 1086, quad tid+16 reads up to 1087

__global__ __launch_bounds__(THREADS) void fir_kernel(
    const float* __restrict__ u, const float* __restrict__ kern,
    float* __restrict__ out, int cols, int out_cols, int K)
{
    __shared__ float s_u[SMEM_U];
    __shared__ float s_w[KMAX];

    const int tid  = threadIdx.x;
    const int row  = blockIdx.y;
    const int base = blockIdx.x * TILE;
    const float* urow = u + (size_t)row * cols;

    // Reversed kernel (correlation with krev == this), zero-padded to KMAX.
    if (tid < KMAX) s_w[tid] = (tid < K) ? kern[K - 1 - tid] : 0.0f;

    // Stage input tile: 272 float4 loads across 256 threads, coalesced.
    #pragma unroll
    for (int q = tid; q < SMEM_U / 4; q += THREADS) {
        const int gi = base + q * 4;
        float4 v;
        if (gi + 3 < cols) {
            v = *reinterpret_cast<const float4*>(urow + gi);
        } else {
            v.x = (gi + 0 < cols) ? urow[gi + 0] : 0.0f;
            v.y = (gi + 1 < cols) ? urow[gi + 1] : 0.0f;
            v.z = (gi + 2 < cols) ? urow[gi + 2] : 0.0f;
            v.w = (gi + 3 < cols) ? urow[gi + 3] : 0.0f;
        }
        reinterpret_cast<float4*>(s_u)[q] = v;
    }
    __syncthreads();

    const float4* su4 = reinterpret_cast<const float4*>(s_u);
    const float4* sw4 = reinterpret_cast<const float4*>(s_w);

    // 4 consecutive outputs per thread; sliding register window of 2 quads.
    float4 q0 = su4[tid];                 // conflict-free: consecutive float4 indices
    float a0 = 0.f, a1 = 0.f, a2 = 0.f, a3 = 0.f;

    #pragma unroll
    for (int m = 0; m < KMAX / 4; ++m) {
        const float4 q1 = su4[tid + m + 1];   // conflict-free
        const float4 wv = sw4[m];             // warp-uniform broadcast
        const float v0 = q0.x, v1 = q0.y, v2 = q0.z, v3 = q0.w;
        const float v4 = q1.x, v5 = q1.y, v6 = q1.z;
        a0 = fmaf(v3, wv.w, fmaf(v2, wv.z, fmaf(v1, wv.y, fmaf(v0, wv.x, a0))));
        a1 = fmaf(v4, wv.w, fmaf(v3, wv.z, fmaf(v2, wv.y, fmaf(v1, wv.x, a1))));
        a2 = fmaf(v5, wv.w, fmaf(v4, wv.z, fmaf(v3, wv.y, fmaf(v2, wv.x, a2))));
        a3 = fmaf(v6, wv.w, fmaf(v5, wv.z, fmaf(v4, wv.y, fmaf(v3, wv.x, a3))));
        q0 = q1;
    }

    const int oc = base + tid * OPT;
    float* orow = out + (size_t)row * out_cols;
    if (oc + 3 < out_cols) {
        float4 r; r.x = a0; r.y = a1; r.z = a2; r.w = a3;
        *reinterpret_cast<float4*>(orow + oc) = r;   // out row base & oc are 16B-aligned
    } else {
        if (oc + 0 < out_cols) orow[oc + 0] = a0;
        if (oc + 1 < out_cols) orow[oc + 1] = a1;
        if (oc + 2 < out_cols) orow[oc + 2] = a2;
        if (oc + 3 < out_cols) orow[oc + 3] = a3;
    }
}

extern "C" void kernel_launch(void* const* d_in, const int* in_sizes, int n_in,
                              void* d_out, int out_size)
{
    const float* u    = (const float*)d_in[0];
    const float* kern = (const float*)d_in[1];
    float*       out  = (float*)d_out;

    const int S0 = in_sizes[0];          // rows * cols
    const int K  = in_sizes[1];          // 61
    // rows*(cols) = S0 ; rows*(cols-K+1) = out_size  =>  rows = (S0-out_size)/(K-1)
    const int rows     = (S0 - out_size) / (K - 1);
    const int cols     = S0 / rows;
    const int out_cols = cols - K + 1;

    dim3 grid((out_cols + TILE - 1) / TILE, rows);
    fir_kernel<<<grid, THREADS>>>(u, kern, out, cols, out_cols, K);
}